// round 14
// baseline (speedup 1.0000x reference)
#include <cuda_runtime.h>
#include <cuda_bf16.h>
#include <cstdint>
#include <cstddef>

typedef unsigned long long ull;
#define BATCH 131072

// ======================= small helpers =======================
__device__ __forceinline__ ull dup2(float v) {
    ull r; asm("mov.b64 %0, {%1, %1};" : "=l"(r) : "r"(__float_as_uint(v))); return r;
}
__device__ __forceinline__ ull pack2(float lo, float hi) {
    ull r; asm("mov.b64 %0, {%1, %2};" : "=l"(r)
               : "r"(__float_as_uint(lo)), "r"(__float_as_uint(hi))); return r;
}
__device__ __forceinline__ void unpack2(ull v, float& lo, float& hi) {
    unsigned a, b; asm("mov.b64 {%0, %1}, %2;" : "=r"(a), "=r"(b) : "l"(v));
    lo = __uint_as_float(a); hi = __uint_as_float(b);
}
__device__ __forceinline__ void fma2(ull& d, ull a, ull b) {
    asm("fma.rn.f32x2 %0, %1, %2, %0;" : "+l"(d) : "l"(a), "l"(b));
}
__device__ __forceinline__ float gelu(float x) {
    return 0.5f * x * (1.0f + erff(x * 0.70710678118654752440f));
}
__device__ __forceinline__ uint32_t smem_u32(const void* p) {
    uint32_t a;
    asm("{ .reg .u64 t; cvta.to.shared.u64 t, %1; cvt.u32.u64 %0, t; }" : "=r"(a) : "l"(p));
    return a;
}
// split float pair into bf16-hi word and bf16-lo (residual) word
__device__ __forceinline__ void cvt_split2(float x, float y, uint32_t& hw, uint32_t& lw) {
    asm("cvt.rn.bf16x2.f32 %0, %1, %2;" : "=r"(hw) : "f"(y), "f"(x));
    float hx = __uint_as_float(hw << 16);
    float hy = __uint_as_float(hw & 0xFFFF0000u);
    float rx = x - hx, ry = y - hy;
    asm("cvt.rn.bf16x2.f32 %0, %1, %2;" : "=r"(lw) : "f"(ry), "f"(rx));
}

#define LDSM_X4(r, adr) \
    asm volatile("ldmatrix.sync.aligned.m8n8.x4.shared.b16 {%0,%1,%2,%3}, [%4];" \
        : "=r"((r)[0]), "=r"((r)[1]), "=r"((r)[2]), "=r"((r)[3]) : "r"(adr))
#define LDSM_X4T(r, adr) \
    asm volatile("ldmatrix.sync.aligned.m8n8.x4.trans.shared.b16 {%0,%1,%2,%3}, [%4];" \
        : "=r"((r)[0]), "=r"((r)[1]), "=r"((r)[2]), "=r"((r)[3]) : "r"(adr))
#define MMA_BF16(d, a, b0, b1) \
    asm volatile("mma.sync.aligned.m16n8k16.row.col.f32.bf16.bf16.f32 " \
        "{%0,%1,%2,%3}, {%4,%5,%6,%7}, {%8,%9}, {%0,%1,%2,%3};" \
        : "+f"((d)[0]), "+f"((d)[1]), "+f"((d)[2]), "+f"((d)[3]) \
        : "r"((a)[0]), "r"((a)[1]), "r"((a)[2]), "r"((a)[3]), "r"(b0), "r"(b1))
#define CP16(dst, src) \
    asm volatile("cp.async.ca.shared.global [%0], [%1], 16;" :: "r"(dst), "l"(src))
#define CP_COMMIT() asm volatile("cp.async.commit_group;" ::: "memory")
#define CP_WAIT1()  asm volatile("cp.async.wait_group 1;" ::: "memory")

// ======================= scratch =======================
__device__ __nv_bfloat16 g_h1h[(size_t)BATCH * 512];
__device__ __nv_bfloat16 g_h1l[(size_t)BATCH * 512];
__device__ __nv_bfloat16 g_w1h[512 * 800], g_w1l[512 * 800];
__device__ __nv_bfloat16 g_w2h[256 * 512], g_w2l[256 * 512];
__device__ float g_mid[(size_t)BATCH * 256];
__device__ float g_pw[(size_t)BATCH * 16];
__device__ float g_mo[(size_t)BATCH * 128];

// ======================= k_wsplit: fp32 W -> bf16 hi/lo (K padded) =======================
__global__ void k_wsplit(const float* __restrict__ W, int Kin, int Kp,
                         __nv_bfloat16* __restrict__ oh, __nv_bfloat16* __restrict__ ol)
{
    const size_t i = (size_t)blockIdx.x * 256 + threadIdx.x;  // over N*Kp
    const int n = (int)(i / Kp), c = (int)(i % Kp);
    float v = (c < Kin) ? W[(size_t)n * Kin + c] : 0.f;
    __nv_bfloat16 h = __float2bfloat16_rn(v);
    float r = v - __bfloat162float(h);
    oh[i] = h;
    ol[i] = __float2bfloat16_rn(r);
}

// ======================= k_hmma2: C = gelu(A @ W^T + b), bf16 3-term split =======================
// BM=64, BN=256, BK=32, 256 thr (8 warps, 2Mx4N grid, warp tile 32x64), 2 CTAs/SM.
#define STR 40
#define SM_AH 0
#define SM_AL 2560
#define SM_W0H 5120
#define SM_W0L 15360
#define SM_W1H 25600
#define SM_W1L 35840
#define SM_TOT_US 46080   // ushorts -> 92160 bytes

__global__ void __launch_bounds__(256, 2) k_hmma2(
    const float* __restrict__ A32,
    const __nv_bfloat16* __restrict__ Ah, const __nv_bfloat16* __restrict__ Al,
    const __nv_bfloat16* __restrict__ Wh, const __nv_bfloat16* __restrict__ Wl,
    const float* __restrict__ bias,
    float* __restrict__ Cf,
    __nv_bfloat16* __restrict__ Ch, __nv_bfloat16* __restrict__ Cl,
    int K, int Kp, int N)
{
    extern __shared__ ushort smu[];
    const uint32_t sb = smem_u32(smu);

    const int tid = threadIdx.x;
    const int lane = tid & 31, wid = tid >> 5;
    const int wm = wid >> 2, wn = wid & 3;
    const int m0 = blockIdx.y << 6, n0 = blockIdx.x << 8;

    const int ar = tid >> 2, aq = (tid & 3) << 3;      // A loader: row 0..63, col base
    const __nv_bfloat16* whp = Wh + (size_t)(n0 + tid) * Kp;
    const __nv_bfloat16* wlp = Wl + (size_t)(n0 + tid) * Kp;
    const uint32_t wdH = sb + (uint32_t)(tid * STR) * 2;

    float acc[2][8][4];
#pragma unroll
    for (int mt = 0; mt < 2; mt++)
#pragma unroll
        for (int nt = 0; nt < 8; nt++)
#pragma unroll
            for (int d = 0; d < 4; d++) acc[mt][nt][d] = 0.f;

    const int nch = Kp >> 5;
    const bool a32 = (A32 != nullptr);
    const float* a32p = a32 ? (A32 + (size_t)(m0 + ar) * K + aq) : nullptr;
    const __nv_bfloat16* ahp = a32 ? nullptr : (Ah + (size_t)(m0 + ar) * Kp + aq);
    const __nv_bfloat16* alp = a32 ? nullptr : (Al + (size_t)(m0 + ar) * Kp + aq);

    float4 pa0, pa1;
    const float4 z4 = make_float4(0.f, 0.f, 0.f, 0.f);
    if (a32) {
        pa0 = (aq < K) ? *(const float4*)(a32p) : z4;
        pa1 = (aq + 4 < K) ? *(const float4*)(a32p + 4) : z4;
    } else {
        pa0 = *(const float4*)(const void*)(ahp);
        pa1 = *(const float4*)(const void*)(alp);
    }
    {
        const uint32_t bufo = (uint32_t)SM_W0H * 2;
#pragma unroll
        for (int i = 0; i < 4; i++) {
            CP16(wdH + bufo + 16 * i, whp + i * 8);
            CP16(wdH + bufo + (SM_W0L - SM_W0H) * 2 + 16 * i, wlp + i * 8);
        }
        CP_COMMIT();
    }

    const int a_r = (lane & 15);
    const int a_k = (lane >> 4) << 3;
    const int b_n = ((lane >> 4) << 3) + (lane & 7);
    const int b_k = ((lane >> 3) & 1) << 3;

    for (int c = 0; c < nch; c++) {
        __syncthreads();
        if (a32) {
            uint32_t h0, l0, h1, l1, h2, l2, h3, l3;
            cvt_split2(pa0.x, pa0.y, h0, l0);
            cvt_split2(pa0.z, pa0.w, h1, l1);
            cvt_split2(pa1.x, pa1.y, h2, l2);
            cvt_split2(pa1.z, pa1.w, h3, l3);
            *(uint2*)&smu[SM_AH + ar * STR + aq]     = make_uint2(h0, h1);
            *(uint2*)&smu[SM_AH + ar * STR + aq + 4] = make_uint2(h2, h3);
            *(uint2*)&smu[SM_AL + ar * STR + aq]     = make_uint2(l0, l1);
            *(uint2*)&smu[SM_AL + ar * STR + aq + 4] = make_uint2(l2, l3);
        } else {
            *(float4*)&smu[SM_AH + ar * STR + aq] = pa0;
            *(float4*)&smu[SM_AL + ar * STR + aq] = pa1;
        }
        if (c + 1 < nch) {
            const uint32_t bufo = ((c + 1) & 1) ? (uint32_t)SM_W1H * 2 : (uint32_t)SM_W0H * 2;
            const int kn = (c + 1) << 5;
#pragma unroll
            for (int i = 0; i < 4; i++) {
                CP16(wdH + bufo + 16 * i, whp + kn + i * 8);
                CP16(wdH + bufo + 20480 + 16 * i, wlp + kn + i * 8);
            }
        }
        CP_COMMIT();
        CP_WAIT1();
        __syncthreads();
        if (c + 1 < nch) {
            const int kn = (c + 1) << 5;
            if (a32) {
                pa0 = (kn + aq < K) ? *(const float4*)(a32p + kn) : z4;
                pa1 = (kn + aq + 4 < K) ? *(const float4*)(a32p + kn + 4) : z4;
            } else {
                pa0 = *(const float4*)(const void*)(ahp + kn);
                pa1 = *(const float4*)(const void*)(alp + kn);
            }
        }
        const int wbH = (c & 1) ? SM_W1H : SM_W0H;
        const int wbL = (c & 1) ? SM_W1L : SM_W0L;
#pragma unroll
        for (int ks = 0; ks < 32; ks += 16) {
            uint32_t ah[2][4], al[2][4];
#pragma unroll
            for (int mt = 0; mt < 2; mt++) {
                const int row = wm * 32 + mt * 16 + a_r;
                const int kc = ks + a_k;
                LDSM_X4(ah[mt], sb + (uint32_t)(SM_AH + row * STR + kc) * 2);
                LDSM_X4(al[mt], sb + (uint32_t)(SM_AL + row * STR + kc) * 2);
            }
            // np-blocked: only 8 B-frag regs live at a time
#pragma unroll
            for (int np = 0; np < 4; np++) {
                uint32_t bh[4], bl[4];
                const int n = wn * 64 + np * 16 + b_n;
                const int kc = ks + b_k;
                LDSM_X4T(bh, sb + (uint32_t)(wbH + n * STR + kc) * 2);
                LDSM_X4T(bl, sb + (uint32_t)(wbL + n * STR + kc) * 2);
#pragma unroll
                for (int mt = 0; mt < 2; mt++)
#pragma unroll
                    for (int q = 0; q < 2; q++) {
                        float* d = acc[mt][np * 2 + q];
                        MMA_BF16(d, ah[mt], bh[q * 2], bh[q * 2 + 1]);
                        MMA_BF16(d, al[mt], bh[q * 2], bh[q * 2 + 1]);
                        MMA_BF16(d, ah[mt], bl[q * 2], bl[q * 2 + 1]);
                    }
            }
        }
    }

    // epilogue
    const int gid = lane >> 2, tig = lane & 3;
#pragma unroll
    for (int nt = 0; nt < 8; nt++) {
        const int col = n0 + wn * 64 + nt * 8 + tig * 2;
        const float b0 = bias[col], b1 = bias[col + 1];
#pragma unroll
        for (int mt = 0; mt < 2; mt++) {
            const size_t r0 = (size_t)m0 + wm * 32 + mt * 16 + gid;
            float v0 = gelu(acc[mt][nt][0] + b0);
            float v1 = gelu(acc[mt][nt][1] + b1);
            float v2 = gelu(acc[mt][nt][2] + b0);
            float v3 = gelu(acc[mt][nt][3] + b1);
            if (Cf) {
                *(float2*)(Cf + r0 * N + col) = make_float2(v0, v1);
                *(float2*)(Cf + (r0 + 8) * N + col) = make_float2(v2, v3);
            } else {
                uint32_t hw, lw;
                cvt_split2(v0, v1, hw, lw);
                *(uint32_t*)(Ch + r0 * N + col) = hw;
                *(uint32_t*)(Cl + r0 * N + col) = lw;
                cvt_split2(v2, v3, hw, lw);
                *(uint32_t*)(Ch + (r0 + 8) * N + col) = hw;
                *(uint32_t*)(Cl + (r0 + 8) * N + col) = lw;
            }
        }
    }
}

// ======================= k_router =======================
__global__ void __launch_bounds__(256) k_router(
    const float* __restrict__ mid, const float* __restrict__ Wr,
    const float* __restrict__ br, float* __restrict__ pw)
{
    __shared__ float Wrs[16][256];
    const int tid = threadIdx.x;
    for (int i = tid; i < 16 * 256; i += 256) Wrs[i >> 8][i & 255] = Wr[i];
    __syncthreads();
    const int w = tid >> 5, l = tid & 31;
    const size_t b = (size_t)blockIdx.x * 8 + w;
    float x8[8];
#pragma unroll
    for (int m = 0; m < 8; m++) x8[m] = mid[b * 256 + m * 32 + l];
    float acc[16];
#pragma unroll
    for (int n = 0; n < 16; n++) {
        float a = 0.f;
#pragma unroll
        for (int m = 0; m < 8; m++) a += x8[m] * Wrs[n][m * 32 + l];
        acc[n] = a;
    }
#pragma unroll
    for (int n = 0; n < 16; n++) {
#pragma unroll
        for (int off = 16; off >= 1; off >>= 1)
            acc[n] += __shfl_xor_sync(0xffffffffu, acc[n], off);
        acc[n] += br[n];
    }
    float mx = acc[0];
#pragma unroll
    for (int n = 1; n < 16; n++) mx = fmaxf(mx, acc[n]);
    float s = 0.f;
#pragma unroll
    for (int n = 0; n < 16; n++) { acc[n] = expf(acc[n] - mx); s += acc[n]; }
    const float inv = 1.f / s;
    float v = 0.f;
#pragma unroll
    for (int n = 0; n < 16; n++) if (l == n) v = acc[n] * inv;
    if (l < 16) pw[b * 16 + l] = v;
}

// ======================= k_mid: fused grouped L3 + routing + gelu =======================
__global__ void __launch_bounds__(256) k_mid(
    const float* __restrict__ mid, const float* __restrict__ W3,
    const float* __restrict__ b3, const float* __restrict__ pw,
    float* __restrict__ mo)
{
    __shared__ float As[16][128];
    __shared__ float Bs[16][64];
    const int tid = threadIdx.x;
    const int m0 = blockIdx.y << 7, n0 = blockIdx.x << 6;
    const int a_ldr = tid >> 1, a_ldk = (tid & 1) << 3;
    const int b_ldr = tid >> 2, b_ldk = (tid & 3) << 2;
    const int w = tid >> 5, l = tid & 31;
    const int fm = ((w & 3) << 5) + ((l & 3) << 3);
    const int fn = ((w >> 2) << 5) + ((l >> 2) << 2);
    const int og = (n0 + fn) >> 5;

    const float* Ap = mid + (size_t)(m0 + a_ldr) * 256 + a_ldk;
    const float* Wp = W3 + (size_t)(n0 + b_ldr) * 256 + b_ldk;

    float pwv[4][8];
#pragma unroll
    for (int g = 0; g < 4; g++)
#pragma unroll
        for (int i = 0; i < 8; i++)
            pwv[g][i] = pw[(size_t)(m0 + fm + i) * 16 + g * 4 + og];

    ull facc[4][4], acc[4][4];
#pragma unroll
    for (int p = 0; p < 4; p++)
#pragma unroll
        for (int j = 0; j < 4; j++) { facc[p][j] = 0ULL; acc[p][j] = 0ULL; }

    float4 a0 = *(const float4*)(Ap);
    float4 a1 = *(const float4*)(Ap + 4);
    float4 w0 = *(const float4*)(Wp);

    for (int t = 0; t < 16; t++) {
        __syncthreads();
        As[a_ldk + 0][a_ldr] = a0.x; As[a_ldk + 1][a_ldr] = a0.y;
        As[a_ldk + 2][a_ldr] = a0.z; As[a_ldk + 3][a_ldr] = a0.w;
        As[a_ldk + 4][a_ldr] = a1.x; As[a_ldk + 5][a_ldr] = a1.y;
        As[a_ldk + 6][a_ldr] = a1.z; As[a_ldk + 7][a_ldr] = a1.w;
        Bs[b_ldk + 0][b_ldr] = w0.x; Bs[b_ldk + 1][b_ldr] = w0.y;
        Bs[b_ldk + 2][b_ldr] = w0.z; Bs[b_ldk + 3][b_ldr] = w0.w;
        __syncthreads();
        if (t < 15) {
            const int t1 = t + 1;
            const int off = (t1 >> 2) * 64 + (t1 & 3) * 16;
            a0 = *(const float4*)(Ap + off);
            a1 = *(const float4*)(Ap + off + 4);
            w0 = *(const float4*)(Wp + off);
        }
#pragma unroll
        for (int kk = 0; kk < 16; kk++) {
            const ulonglong2* ap = (const ulonglong2*)&As[kk][fm];
            ulonglong2 av0 = ap[0], av1 = ap[1];
            float4 bq = *(const float4*)&Bs[kk][fn];
            ull a[4] = {av0.x, av0.y, av1.x, av1.y};
            ull b[4] = {dup2(bq.x), dup2(bq.y), dup2(bq.z), dup2(bq.w)};
#pragma unroll
            for (int p = 0; p < 4; p++)
#pragma unroll
                for (int j = 0; j < 4; j++) fma2(acc[p][j], a[p], b[j]);
        }
        if ((t & 3) == 3) {
            const int g = t >> 2;
#pragma unroll
            for (int p = 0; p < 4; p++) {
                ull pwp = pack2(pwv[g][2 * p], pwv[g][2 * p + 1]);
#pragma unroll
                for (int j = 0; j < 4; j++) { fma2(facc[p][j], pwp, acc[p][j]); acc[p][j] = 0ULL; }
            }
        }
    }

    float psum[8];
#pragma unroll
    for (int i = 0; i < 8; i++)
        psum[i] = pwv[0][i] + pwv[1][i] + pwv[2][i] + pwv[3][i];
    const int nb = n0 + fn;
    float b3v[4] = {b3[nb], b3[nb + 1], b3[nb + 2], b3[nb + 3]};
#pragma unroll
    for (int p = 0; p < 4; p++) {
        const size_t row = (size_t)m0 + fm + (p << 1);
        float o0[4], o1[4];
#pragma unroll
        for (int j = 0; j < 4; j++) {
            float lo, hi; unpack2(facc[p][j], lo, hi);
            o0[j] = gelu(lo + b3v[j] * psum[2 * p]);
            o1[j] = gelu(hi + b3v[j] * psum[2 * p + 1]);
        }
        *(float4*)(mo + row * 128 + nb)       = make_float4(o0[0], o0[1], o0[2], o0[3]);
        *(float4*)(mo + (row + 1) * 128 + nb) = make_float4(o1[0], o1[1], o1[2], o1[3]);
    }
}

// ======================= fused tail: L4 L5 L6 =======================
#define XS_STR 132
#define W4_STR 132
#define W5_STR 68
#define W6_STR 36
#define H4_STR 68
#define H5_STR 36
#define TAIL_SMEM_FLOATS 18642
__global__ void __launch_bounds__(256) k_tail(
    const float* __restrict__ mo,
    const float* __restrict__ W4, const float* __restrict__ b4,
    const float* __restrict__ W5, const float* __restrict__ b5,
    const float* __restrict__ W6, const float* __restrict__ b6,
    float* __restrict__ out)
{
    extern __shared__ float smf[];
    float* xs  = smf;
    float* W4s = xs  + 32 * XS_STR;
    float* W5s = W4s + 64 * W4_STR;
    float* W6s = W5s + 32 * W5_STR;
    float* h4s = W6s + 10 * W6_STR;
    float* h5s = h4s + 32 * H4_STR;
    float* bs  = h5s + 32 * H5_STR;
    const int tid = threadIdx.x;
    for (int i = tid; i < 64 * 128; i += 256) W4s[(i >> 7) * W4_STR + (i & 127)] = W4[i];
    for (int i = tid; i < 32 * 64;  i += 256) W5s[(i >> 6) * W5_STR + (i & 63)]  = W5[i];
    for (int i = tid; i < 10 * 32;  i += 256) W6s[(i >> 5) * W6_STR + (i & 31)]  = W6[i];
    if (tid < 64) bs[tid] = b4[tid];
    else if (tid < 96) bs[tid] = b5[tid - 64];
    else if (tid < 106) bs[tid] = b6[tid - 96];
    const size_t row0 = (size_t)blockIdx.x * 32;
    for (int i = tid; i < 32 * 128; i += 256) xs[(i >> 7) * XS_STR + (i & 127)] = mo[row0 * 128 + i];
    __syncthreads();
    const int r = tid >> 3, s = tid & 7;
#pragma unroll
    for (int n8 = 0; n8 < 8; n8++) {
        const int n = s + 8 * n8;
        float a = bs[n];
#pragma unroll 8
        for (int k = 0; k < 128; k += 4) {
            float4 xv = *(const float4*)&xs[r * XS_STR + k];
            float4 wv = *(const float4*)&W4s[n * W4_STR + k];
            a += xv.x * wv.x + xv.y * wv.y + xv.z * wv.z + xv.w * wv.w;
        }
        h4s[r * H4_STR + n] = gelu(a);
    }
    __syncthreads();
#pragma unroll
    for (int n4 = 0; n4 < 4; n4++) {
        const int n = s + 8 * n4;
        float a = bs[64 + n];
#pragma unroll
        for (int k = 0; k < 64; k += 4) {
            float4 xv = *(const float4*)&h4s[r * H4_STR + k];
            float4 wv = *(const float4*)&W5s[n * W5_STR + k];
            a += xv.x * wv.x + xv.y * wv.y + xv.z * wv.z + xv.w * wv.w;
        }
        h5s[r * H5_STR + n] = gelu(a);
    }
    __syncthreads();
    if (s < 5) {
#pragma unroll
        for (int q = 0; q < 2; q++) {
            const int n = s + 5 * q;
            float a = bs[96 + n];
#pragma unroll
            for (int k = 0; k < 32; k++) a += h5s[r * H5_STR + k] * W6s[n * W6_STR + k];
            out[(row0 + r) * 10 + n] = a;
        }
    }
}

// ======================= launch =======================
extern "C" void kernel_launch(void* const* d_in, const int* in_sizes, int n_in,
                              void* d_out, int out_size)
{
    const float* x  = (const float*)d_in[0];
    const float* W1 = (const float*)d_in[1];  const float* b1 = (const float*)d_in[2];
    const float* W2 = (const float*)d_in[3];  const float* b2 = (const float*)d_in[4];
    const float* W3 = (const float*)d_in[5];  const float* b3 = (const float*)d_in[6];
    const float* W4 = (const float*)d_in[7];  const float* b4 = (const float*)d_in[8];
    const float* W5 = (const float*)d_in[9];  const float* b5 = (const float*)d_in[10];
    const float* W6 = (const float*)d_in[11]; const float* b6 = (const float*)d_in[12];
    const float* Wr = (const float*)d_in[13]; const float* br = (const float*)d_in[14];
    float* out = (float*)d_out;

    __nv_bfloat16 *h1h, *h1l, *w1h, *w1l, *w2h, *w2l;
    float *mid, *pw, *mo;
    cudaGetSymbolAddress((void**)&h1h, g_h1h);
    cudaGetSymbolAddress((void**)&h1l, g_h1l);
    cudaGetSymbolAddress((void**)&w1h, g_w1h);
    cudaGetSymbolAddress((void**)&w1l, g_w1l);
    cudaGetSymbolAddress((void**)&w2h, g_w2h);
    cudaGetSymbolAddress((void**)&w2l, g_w2l);
    cudaGetSymbolAddress((void**)&mid, g_mid);
    cudaGetSymbolAddress((void**)&pw,  g_pw);
    cudaGetSymbolAddress((void**)&mo,  g_mo);

    cudaFuncSetAttribute(k_hmma2, cudaFuncAttributeMaxDynamicSharedMemorySize, SM_TOT_US * 2);
    cudaFuncSetAttribute(k_tail, cudaFuncAttributeMaxDynamicSharedMemorySize,
                         TAIL_SMEM_FLOATS * 4);

    // weight splits (tiny)
    k_wsplit<<<512 * 800 / 256, 256>>>(W1, 784, 800, w1h, w1l);
    k_wsplit<<<256 * 512 / 256, 256>>>(W2, 512, 512, w2h, w2l);

    // L1: [B,784] -> [B,512] bf16-split HMMA, output split bf16
    k_hmma2<<<dim3(2, BATCH / 64), 256, SM_TOT_US * 2>>>(
        x, nullptr, nullptr, w1h, w1l, b1, nullptr, h1h, h1l, 784, 800, 512);
    // L2: [B,512] -> [B,256], bf16 input, fp32 output
    k_hmma2<<<dim3(1, BATCH / 64), 256, SM_TOT_US * 2>>>(
        nullptr, h1h, h1l, w2h, w2l, b2, mid, nullptr, nullptr, 512, 512, 256);
    // router
    k_router<<<BATCH / 8, 256>>>(mid, Wr, br, pw);
    // fused grouped middle layer
    k_mid<<<dim3(2, BATCH / 128), 256>>>(mid, W3, b3, pw, mo);
    // fused L4/L5/L6
    k_tail<<<BATCH / 32, 256, TAIL_SMEM_FLOATS * 4>>>(mo, W4, b4, W5, b5, W6, b6, out);
}

// round 15
// speedup vs baseline: 1.1613x; 1.1613x over previous
#include <cuda_runtime.h>
#include <cuda_bf16.h>
#include <cstdint>
#include <cstddef>

typedef unsigned long long ull;
#define BATCH 131072

// ======================= small helpers =======================
__device__ __forceinline__ ull dup2(float v) {
    ull r; asm("mov.b64 %0, {%1, %1};" : "=l"(r) : "r"(__float_as_uint(v))); return r;
}
__device__ __forceinline__ ull pack2(float lo, float hi) {
    ull r; asm("mov.b64 %0, {%1, %2};" : "=l"(r)
               : "r"(__float_as_uint(lo)), "r"(__float_as_uint(hi))); return r;
}
__device__ __forceinline__ void unpack2(ull v, float& lo, float& hi) {
    unsigned a, b; asm("mov.b64 {%0, %1}, %2;" : "=r"(a), "=r"(b) : "l"(v));
    lo = __uint_as_float(a); hi = __uint_as_float(b);
}
__device__ __forceinline__ void fma2(ull& d, ull a, ull b) {
    asm("fma.rn.f32x2 %0, %1, %2, %0;" : "+l"(d) : "l"(a), "l"(b));
}
__device__ __forceinline__ float gelu(float x) {
    return 0.5f * x * (1.0f + erff(x * 0.70710678118654752440f));
}
__device__ __forceinline__ uint32_t smem_u32(const void* p) {
    uint32_t a;
    asm("{ .reg .u64 t; cvta.to.shared.u64 t, %1; cvt.u32.u64 %0, t; }" : "=r"(a) : "l"(p));
    return a;
}
// split float pair into bf16-hi word and bf16-lo (residual) word
__device__ __forceinline__ void cvt_split2(float x, float y, uint32_t& hw, uint32_t& lw) {
    asm("cvt.rn.bf16x2.f32 %0, %1, %2;" : "=r"(hw) : "f"(y), "f"(x));
    float hx = __uint_as_float(hw << 16);
    float hy = __uint_as_float(hw & 0xFFFF0000u);
    float rx = x - hx, ry = y - hy;
    asm("cvt.rn.bf16x2.f32 %0, %1, %2;" : "=r"(lw) : "f"(ry), "f"(rx));
}

#define LDSM_X4(r, adr) \
    asm volatile("ldmatrix.sync.aligned.m8n8.x4.shared.b16 {%0,%1,%2,%3}, [%4];" \
        : "=r"((r)[0]), "=r"((r)[1]), "=r"((r)[2]), "=r"((r)[3]) : "r"(adr))
#define LDSM_X4T(r, adr) \
    asm volatile("ldmatrix.sync.aligned.m8n8.x4.trans.shared.b16 {%0,%1,%2,%3}, [%4];" \
        : "=r"((r)[0]), "=r"((r)[1]), "=r"((r)[2]), "=r"((r)[3]) : "r"(adr))
#define MMA_BF16(d, a, b0, b1) \
    asm volatile("mma.sync.aligned.m16n8k16.row.col.f32.bf16.bf16.f32 " \
        "{%0,%1,%2,%3}, {%4,%5,%6,%7}, {%8,%9}, {%0,%1,%2,%3};" \
        : "+f"((d)[0]), "+f"((d)[1]), "+f"((d)[2]), "+f"((d)[3]) \
        : "r"((a)[0]), "r"((a)[1]), "r"((a)[2]), "r"((a)[3]), "r"(b0), "r"(b1))
#define CP16(dst, src) \
    asm volatile("cp.async.ca.shared.global [%0], [%1], 16;" :: "r"(dst), "l"(src))
#define CP_COMMIT() asm volatile("cp.async.commit_group;" ::: "memory")
#define CP_WAIT1()  asm volatile("cp.async.wait_group 1;" ::: "memory")

// ======================= scratch =======================
__device__ __nv_bfloat16 g_h1h[(size_t)BATCH * 512];
__device__ __nv_bfloat16 g_h1l[(size_t)BATCH * 512];
__device__ __nv_bfloat16 g_w1h[512 * 800], g_w1l[512 * 800];
__device__ __nv_bfloat16 g_w2h[256 * 512], g_w2l[256 * 512];
__device__ float g_mid[(size_t)BATCH * 256];
__device__ float g_pw[(size_t)BATCH * 16];
__device__ float g_mo[(size_t)BATCH * 128];

// ======================= k_wsplit: fp32 W -> bf16 hi/lo (K padded) =======================
__global__ void k_wsplit(const float* __restrict__ W, int Kin, int Kp,
                         __nv_bfloat16* __restrict__ oh, __nv_bfloat16* __restrict__ ol)
{
    const size_t i = (size_t)blockIdx.x * 256 + threadIdx.x;  // over N*Kp
    const int n = (int)(i / Kp), c = (int)(i % Kp);
    float v = (c < Kin) ? W[(size_t)n * Kin + c] : 0.f;
    __nv_bfloat16 h = __float2bfloat16_rn(v);
    float r = v - __bfloat162float(h);
    oh[i] = h;
    ol[i] = __float2bfloat16_rn(r);
}

// ======================= k_hmma2: C = gelu(A @ W^T + b), bf16 3-term split =======================
// CTA 128x256, BK=32, 256 thr (8 warps in 2Mx4N, warp tile 64x64). 1 CTA/SM.
// 85 B smem traffic per MMA (vs 256 at 32x64 warp tiles) -> tensor-bound.
#define STR 40
#define SM_AH 0            // 128*40 = 5120 us
#define SM_AL 5120
#define SM_W0H 10240       // 256*40 = 10240 us
#define SM_W0L 20480
#define SM_W1H 30720
#define SM_W1L 40960
#define SM_TOT_US 51200    // ushorts -> 102400 bytes

__global__ void __launch_bounds__(256) k_hmma2(
    const float* __restrict__ A32,
    const __nv_bfloat16* __restrict__ Ah, const __nv_bfloat16* __restrict__ Al,
    const __nv_bfloat16* __restrict__ Wh, const __nv_bfloat16* __restrict__ Wl,
    const float* __restrict__ bias,
    float* __restrict__ Cf,
    __nv_bfloat16* __restrict__ Ch, __nv_bfloat16* __restrict__ Cl,
    int K, int Kp, int N)
{
    extern __shared__ ushort smu[];
    const uint32_t sb = smem_u32(smu);

    const int tid = threadIdx.x;
    const int lane = tid & 31, wid = tid >> 5;
    const int wm = wid >> 2, wn = wid & 3;           // 2 x 4 warp grid
    const int m0 = blockIdx.y << 7, n0 = blockIdx.x << 8;

    // A loader: 128 rows, 2 threads/row, 16 k each
    const int ar = tid >> 1, aq = (tid & 1) << 4;
    // W loader: 256 rows, 1 thread/row, 32 k hi + 32 k lo via cp.async
    const __nv_bfloat16* whp = Wh + (size_t)(n0 + tid) * Kp;
    const __nv_bfloat16* wlp = Wl + (size_t)(n0 + tid) * Kp;
    const uint32_t wdH = sb + (uint32_t)(tid * STR) * 2;

    float acc[4][8][4];
#pragma unroll
    for (int mt = 0; mt < 4; mt++)
#pragma unroll
        for (int nt = 0; nt < 8; nt++)
#pragma unroll
            for (int d = 0; d < 4; d++) acc[mt][nt][d] = 0.f;

    const int nch = Kp >> 5;
    const bool a32 = (A32 != nullptr);
    const float* a32p = a32 ? (A32 + (size_t)(m0 + ar) * K + aq) : nullptr;
    const __nv_bfloat16* ahp = a32 ? nullptr : (Ah + (size_t)(m0 + ar) * Kp + aq);
    const __nv_bfloat16* alp = a32 ? nullptr : (Al + (size_t)(m0 + ar) * Kp + aq);

    // A prefetch regs: a32 -> 16 floats; bf16 -> pa[0..1]=hi(16), pa[2..3]=lo(16)
    float4 pa[4];
    const float4 z4 = make_float4(0.f, 0.f, 0.f, 0.f);
    if (a32) {
#pragma unroll
        for (int i = 0; i < 4; i++)
            pa[i] = (aq + i * 4 < K) ? *(const float4*)(a32p + i * 4) : z4;
    } else {
        pa[0] = *(const float4*)(const void*)(ahp);
        pa[1] = *(const float4*)(const void*)(ahp + 8);
        pa[2] = *(const float4*)(const void*)(alp);
        pa[3] = *(const float4*)(const void*)(alp + 8);
    }
    // issue W chunk 0 into buffer 0
    {
        const uint32_t bufo = (uint32_t)SM_W0H * 2;
#pragma unroll
        for (int i = 0; i < 4; i++) {
            CP16(wdH + bufo + 16 * i, whp + i * 8);
            CP16(wdH + bufo + 20480 + 16 * i, wlp + i * 8);   // lo block offset 10240 us
        }
        CP_COMMIT();
    }

    const int a_r = (lane & 15);
    const int a_k = (lane >> 4) << 3;
    const int b_n = ((lane >> 4) << 3) + (lane & 7);
    const int b_k = ((lane >> 3) & 1) << 3;

    for (int c = 0; c < nch; c++) {
        __syncthreads();
        // store A regs -> smem (single-buffered)
        if (a32) {
            uint32_t h[8], l[8];
            cvt_split2(pa[0].x, pa[0].y, h[0], l[0]);
            cvt_split2(pa[0].z, pa[0].w, h[1], l[1]);
            cvt_split2(pa[1].x, pa[1].y, h[2], l[2]);
            cvt_split2(pa[1].z, pa[1].w, h[3], l[3]);
            cvt_split2(pa[2].x, pa[2].y, h[4], l[4]);
            cvt_split2(pa[2].z, pa[2].w, h[5], l[5]);
            cvt_split2(pa[3].x, pa[3].y, h[6], l[6]);
            cvt_split2(pa[3].z, pa[3].w, h[7], l[7]);
            *(uint2*)&smu[SM_AH + ar * STR + aq]      = make_uint2(h[0], h[1]);
            *(uint2*)&smu[SM_AH + ar * STR + aq + 4]  = make_uint2(h[2], h[3]);
            *(uint2*)&smu[SM_AH + ar * STR + aq + 8]  = make_uint2(h[4], h[5]);
            *(uint2*)&smu[SM_AH + ar * STR + aq + 12] = make_uint2(h[6], h[7]);
            *(uint2*)&smu[SM_AL + ar * STR + aq]      = make_uint2(l[0], l[1]);
            *(uint2*)&smu[SM_AL + ar * STR + aq + 4]  = make_uint2(l[2], l[3]);
            *(uint2*)&smu[SM_AL + ar * STR + aq + 8]  = make_uint2(l[4], l[5]);
            *(uint2*)&smu[SM_AL + ar * STR + aq + 12] = make_uint2(l[6], l[7]);
        } else {
            *(float4*)&smu[SM_AH + ar * STR + aq]     = pa[0];
            *(float4*)&smu[SM_AH + ar * STR + aq + 8] = pa[1];
            *(float4*)&smu[SM_AL + ar * STR + aq]     = pa[2];
            *(float4*)&smu[SM_AL + ar * STR + aq + 8] = pa[3];
        }
        // issue W chunk c+1 into other buffer
        if (c + 1 < nch) {
            const uint32_t bufo = ((c + 1) & 1) ? (uint32_t)SM_W1H * 2 : (uint32_t)SM_W0H * 2;
            const int kn = (c + 1) << 5;
#pragma unroll
            for (int i = 0; i < 4; i++) {
                CP16(wdH + bufo + 16 * i, whp + kn + i * 8);
                CP16(wdH + bufo + 20480 + 16 * i, wlp + kn + i * 8);
            }
        }
        CP_COMMIT();
        CP_WAIT1();
        __syncthreads();
        // prefetch A chunk c+1
        if (c + 1 < nch) {
            const int kn = (c + 1) << 5;
            if (a32) {
#pragma unroll
                for (int i = 0; i < 4; i++)
                    pa[i] = (kn + aq + i * 4 < K) ? *(const float4*)(a32p + kn + i * 4) : z4;
            } else {
                pa[0] = *(const float4*)(const void*)(ahp + kn);
                pa[1] = *(const float4*)(const void*)(ahp + kn + 8);
                pa[2] = *(const float4*)(const void*)(alp + kn);
                pa[3] = *(const float4*)(const void*)(alp + kn + 8);
            }
        }
        // compute on buffer c&1
        const int wbH = (c & 1) ? SM_W1H : SM_W0H;
        const int wbL = (c & 1) ? SM_W1L : SM_W0L;
#pragma unroll
        for (int ks = 0; ks < 32; ks += 16) {
            uint32_t ah[4][4], al[4][4];
#pragma unroll
            for (int mt = 0; mt < 4; mt++) {
                const int row = wm * 64 + mt * 16 + a_r;
                const int kc = ks + a_k;
                LDSM_X4(ah[mt], sb + (uint32_t)(SM_AH + row * STR + kc) * 2);
                LDSM_X4(al[mt], sb + (uint32_t)(SM_AL + row * STR + kc) * 2);
            }
#pragma unroll
            for (int np = 0; np < 4; np++) {
                uint32_t bh[4], bl[4];
                const int n = wn * 64 + np * 16 + b_n;
                const int kc = ks + b_k;
                LDSM_X4T(bh, sb + (uint32_t)(wbH + n * STR + kc) * 2);
                LDSM_X4T(bl, sb + (uint32_t)(wbL + n * STR + kc) * 2);
#pragma unroll
                for (int mt = 0; mt < 4; mt++)
#pragma unroll
                    for (int q = 0; q < 2; q++) {
                        float* d = acc[mt][np * 2 + q];
                        MMA_BF16(d, ah[mt], bh[q * 2], bh[q * 2 + 1]);
                        MMA_BF16(d, al[mt], bh[q * 2], bh[q * 2 + 1]);
                        MMA_BF16(d, ah[mt], bl[q * 2], bl[q * 2 + 1]);
                    }
            }
        }
    }

    // epilogue
    const int gid = lane >> 2, tig = lane & 3;
#pragma unroll
    for (int nt = 0; nt < 8; nt++) {
        const int col = n0 + wn * 64 + nt * 8 + tig * 2;
        const float b0 = bias[col], b1 = bias[col + 1];
#pragma unroll
        for (int mt = 0; mt < 4; mt++) {
            const size_t r0 = (size_t)m0 + wm * 64 + mt * 16 + gid;
            float v0 = gelu(acc[mt][nt][0] + b0);
            float v1 = gelu(acc[mt][nt][1] + b1);
            float v2 = gelu(acc[mt][nt][2] + b0);
            float v3 = gelu(acc[mt][nt][3] + b1);
            if (Cf) {
                *(float2*)(Cf + r0 * N + col) = make_float2(v0, v1);
                *(float2*)(Cf + (r0 + 8) * N + col) = make_float2(v2, v3);
            } else {
                uint32_t hw, lw;
                cvt_split2(v0, v1, hw, lw);
                *(uint32_t*)(Ch + r0 * N + col) = hw;
                *(uint32_t*)(Cl + r0 * N + col) = lw;
                cvt_split2(v2, v3, hw, lw);
                *(uint32_t*)(Ch + (r0 + 8) * N + col) = hw;
                *(uint32_t*)(Cl + (r0 + 8) * N + col) = lw;
            }
        }
    }
}

// ======================= k_router =======================
__global__ void __launch_bounds__(256) k_router(
    const float* __restrict__ mid, const float* __restrict__ Wr,
    const float* __restrict__ br, float* __restrict__ pw)
{
    __shared__ float Wrs[16][256];
    const int tid = threadIdx.x;
    for (int i = tid; i < 16 * 256; i += 256) Wrs[i >> 8][i & 255] = Wr[i];
    __syncthreads();
    const int w = tid >> 5, l = tid & 31;
    const size_t b = (size_t)blockIdx.x * 8 + w;
    float x8[8];
#pragma unroll
    for (int m = 0; m < 8; m++) x8[m] = mid[b * 256 + m * 32 + l];
    float acc[16];
#pragma unroll
    for (int n = 0; n < 16; n++) {
        float a = 0.f;
#pragma unroll
        for (int m = 0; m < 8; m++) a += x8[m] * Wrs[n][m * 32 + l];
        acc[n] = a;
    }
#pragma unroll
    for (int n = 0; n < 16; n++) {
#pragma unroll
        for (int off = 16; off >= 1; off >>= 1)
            acc[n] += __shfl_xor_sync(0xffffffffu, acc[n], off);
        acc[n] += br[n];
    }
    float mx = acc[0];
#pragma unroll
    for (int n = 1; n < 16; n++) mx = fmaxf(mx, acc[n]);
    float s = 0.f;
#pragma unroll
    for (int n = 0; n < 16; n++) { acc[n] = expf(acc[n] - mx); s += acc[n]; }
    const float inv = 1.f / s;
    float v = 0.f;
#pragma unroll
    for (int n = 0; n < 16; n++) if (l == n) v = acc[n] * inv;
    if (l < 16) pw[b * 16 + l] = v;
}

// ======================= k_mid: fused grouped L3 + routing + gelu =======================
__global__ void __launch_bounds__(256) k_mid(
    const float* __restrict__ mid, const float* __restrict__ W3,
    const float* __restrict__ b3, const float* __restrict__ pw,
    float* __restrict__ mo)
{
    __shared__ float As[16][128];
    __shared__ float Bs[16][64];
    const int tid = threadIdx.x;
    const int m0 = blockIdx.y << 7, n0 = blockIdx.x << 6;
    const int a_ldr = tid >> 1, a_ldk = (tid & 1) << 3;
    const int b_ldr = tid >> 2, b_ldk = (tid & 3) << 2;
    const int w = tid >> 5, l = tid & 31;
    const int fm = ((w & 3) << 5) + ((l & 3) << 3);
    const int fn = ((w >> 2) << 5) + ((l >> 2) << 2);
    const int og = (n0 + fn) >> 5;

    const float* Ap = mid + (size_t)(m0 + a_ldr) * 256 + a_ldk;
    const float* Wp = W3 + (size_t)(n0 + b_ldr) * 256 + b_ldk;

    float pwv[4][8];
#pragma unroll
    for (int g = 0; g < 4; g++)
#pragma unroll
        for (int i = 0; i < 8; i++)
            pwv[g][i] = pw[(size_t)(m0 + fm + i) * 16 + g * 4 + og];

    ull facc[4][4], acc[4][4];
#pragma unroll
    for (int p = 0; p < 4; p++)
#pragma unroll
        for (int j = 0; j < 4; j++) { facc[p][j] = 0ULL; acc[p][j] = 0ULL; }

    float4 a0 = *(const float4*)(Ap);
    float4 a1 = *(const float4*)(Ap + 4);
    float4 w0 = *(const float4*)(Wp);

    for (int t = 0; t < 16; t++) {
        __syncthreads();
        As[a_ldk + 0][a_ldr] = a0.x; As[a_ldk + 1][a_ldr] = a0.y;
        As[a_ldk + 2][a_ldr] = a0.z; As[a_ldk + 3][a_ldr] = a0.w;
        As[a_ldk + 4][a_ldr] = a1.x; As[a_ldk + 5][a_ldr] = a1.y;
        As[a_ldk + 6][a_ldr] = a1.z; As[a_ldk + 7][a_ldr] = a1.w;
        Bs[b_ldk + 0][b_ldr] = w0.x; Bs[b_ldk + 1][b_ldr] = w0.y;
        Bs[b_ldk + 2][b_ldr] = w0.z; Bs[b_ldk + 3][b_ldr] = w0.w;
        __syncthreads();
        if (t < 15) {
            const int t1 = t + 1;
            const int off = (t1 >> 2) * 64 + (t1 & 3) * 16;
            a0 = *(const float4*)(Ap + off);
            a1 = *(const float4*)(Ap + off + 4);
            w0 = *(const float4*)(Wp + off);
        }
#pragma unroll
        for (int kk = 0; kk < 16; kk++) {
            const ulonglong2* ap = (const ulonglong2*)&As[kk][fm];
            ulonglong2 av0 = ap[0], av1 = ap[1];
            float4 bq = *(const float4*)&Bs[kk][fn];
            ull a[4] = {av0.x, av0.y, av1.x, av1.y};
            ull b[4] = {dup2(bq.x), dup2(bq.y), dup2(bq.z), dup2(bq.w)};
#pragma unroll
            for (int p = 0; p < 4; p++)
#pragma unroll
                for (int j = 0; j < 4; j++) fma2(acc[p][j], a[p], b[j]);
        }
        if ((t & 3) == 3) {
            const int g = t >> 2;
#pragma unroll
            for (int p = 0; p < 4; p++) {
                ull pwp = pack2(pwv[g][2 * p], pwv[g][2 * p + 1]);
#pragma unroll
                for (int j = 0; j < 4; j++) { fma2(facc[p][j], pwp, acc[p][j]); acc[p][j] = 0ULL; }
            }
        }
    }

    float psum[8];
#pragma unroll
    for (int i = 0; i < 8; i++)
        psum[i] = pwv[0][i] + pwv[1][i] + pwv[2][i] + pwv[3][i];
    const int nb = n0 + fn;
    float b3v[4] = {b3[nb], b3[nb + 1], b3[nb + 2], b3[nb + 3]};
#pragma unroll
    for (int p = 0; p < 4; p++) {
        const size_t row = (size_t)m0 + fm + (p << 1);
        float o0[4], o1[4];
#pragma unroll
        for (int j = 0; j < 4; j++) {
            float lo, hi; unpack2(facc[p][j], lo, hi);
            o0[j] = gelu(lo + b3v[j] * psum[2 * p]);
            o1[j] = gelu(hi + b3v[j] * psum[2 * p + 1]);
        }
        *(float4*)(mo + row * 128 + nb)       = make_float4(o0[0], o0[1], o0[2], o0[3]);
        *(float4*)(mo + (row + 1) * 128 + nb) = make_float4(o1[0], o1[1], o1[2], o1[3]);
    }
}

// ======================= fused tail: L4 L5 L6 =======================
#define XS_STR 132
#define W4_STR 132
#define W5_STR 68
#define W6_STR 36
#define H4_STR 68
#define H5_STR 36
#define TAIL_SMEM_FLOATS 18642
__global__ void __launch_bounds__(256) k_tail(
    const float* __restrict__ mo,
    const float* __restrict__ W4, const float* __restrict__ b4,
    const float* __restrict__ W5, const float* __restrict__ b5,
    const float* __restrict__ W6, const float* __restrict__ b6,
    float* __restrict__ out)
{
    extern __shared__ float smf[];
    float* xs  = smf;
    float* W4s = xs  + 32 * XS_STR;
    float* W5s = W4s + 64 * W4_STR;
    float* W6s = W5s + 32 * W5_STR;
    float* h4s = W6s + 10 * W6_STR;
    float* h5s = h4s + 32 * H4_STR;
    float* bs  = h5s + 32 * H5_STR;
    const int tid = threadIdx.x;
    for (int i = tid; i < 64 * 128; i += 256) W4s[(i >> 7) * W4_STR + (i & 127)] = W4[i];
    for (int i = tid; i < 32 * 64;  i += 256) W5s[(i >> 6) * W5_STR + (i & 63)]  = W5[i];
    for (int i = tid; i < 10 * 32;  i += 256) W6s[(i >> 5) * W6_STR + (i & 31)]  = W6[i];
    if (tid < 64) bs[tid] = b4[tid];
    else if (tid < 96) bs[tid] = b5[tid - 64];
    else if (tid < 106) bs[tid] = b6[tid - 96];
    const size_t row0 = (size_t)blockIdx.x * 32;
    for (int i = tid; i < 32 * 128; i += 256) xs[(i >> 7) * XS_STR + (i & 127)] = mo[row0 * 128 + i];
    __syncthreads();
    const int r = tid >> 3, s = tid & 7;
#pragma unroll
    for (int n8 = 0; n8 < 8; n8++) {
        const int n = s + 8 * n8;
        float a = bs[n];
#pragma unroll 8
        for (int k = 0; k < 128; k += 4) {
            float4 xv = *(const float4*)&xs[r * XS_STR + k];
            float4 wv = *(const float4*)&W4s[n * W4_STR + k];
            a += xv.x * wv.x + xv.y * wv.y + xv.z * wv.z + xv.w * wv.w;
        }
        h4s[r * H4_STR + n] = gelu(a);
    }
    __syncthreads();
#pragma unroll
    for (int n4 = 0; n4 < 4; n4++) {
        const int n = s + 8 * n4;
        float a = bs[64 + n];
#pragma unroll
        for (int k = 0; k < 64; k += 4) {
            float4 xv = *(const float4*)&h4s[r * H4_STR + k];
            float4 wv = *(const float4*)&W5s[n * W5_STR + k];
            a += xv.x * wv.x + xv.y * wv.y + xv.z * wv.z + xv.w * wv.w;
        }
        h5s[r * H5_STR + n] = gelu(a);
    }
    __syncthreads();
    if (s < 5) {
#pragma unroll
        for (int q = 0; q < 2; q++) {
            const int n = s + 5 * q;
            float a = bs[96 + n];
#pragma unroll
            for (int k = 0; k < 32; k++) a += h5s[r * H5_STR + k] * W6s[n * W6_STR + k];
            out[(row0 + r) * 10 + n] = a;
        }
    }
}

// ======================= launch =======================
extern "C" void kernel_launch(void* const* d_in, const int* in_sizes, int n_in,
                              void* d_out, int out_size)
{
    const float* x  = (const float*)d_in[0];
    const float* W1 = (const float*)d_in[1];  const float* b1 = (const float*)d_in[2];
    const float* W2 = (const float*)d_in[3];  const float* b2 = (const float*)d_in[4];
    const float* W3 = (const float*)d_in[5];  const float* b3 = (const float*)d_in[6];
    const float* W4 = (const float*)d_in[7];  const float* b4 = (const float*)d_in[8];
    const float* W5 = (const float*)d_in[9];  const float* b5 = (const float*)d_in[10];
    const float* W6 = (const float*)d_in[11]; const float* b6 = (const float*)d_in[12];
    const float* Wr = (const float*)d_in[13]; const float* br = (const float*)d_in[14];
    float* out = (float*)d_out;

    __nv_bfloat16 *h1h, *h1l, *w1h, *w1l, *w2h, *w2l;
    float *mid, *pw, *mo;
    cudaGetSymbolAddress((void**)&h1h, g_h1h);
    cudaGetSymbolAddress((void**)&h1l, g_h1l);
    cudaGetSymbolAddress((void**)&w1h, g_w1h);
    cudaGetSymbolAddress((void**)&w1l, g_w1l);
    cudaGetSymbolAddress((void**)&w2h, g_w2h);
    cudaGetSymbolAddress((void**)&w2l, g_w2l);
    cudaGetSymbolAddress((void**)&mid, g_mid);
    cudaGetSymbolAddress((void**)&pw,  g_pw);
    cudaGetSymbolAddress((void**)&mo,  g_mo);

    cudaFuncSetAttribute(k_hmma2, cudaFuncAttributeMaxDynamicSharedMemorySize, SM_TOT_US * 2);
    cudaFuncSetAttribute(k_tail, cudaFuncAttributeMaxDynamicSharedMemorySize,
                         TAIL_SMEM_FLOATS * 4);

    // weight splits (tiny)
    k_wsplit<<<512 * 800 / 256, 256>>>(W1, 784, 800, w1h, w1l);
    k_wsplit<<<256 * 512 / 256, 256>>>(W2, 512, 512, w2h, w2l);

    // L1: [B,784] -> [B,512] bf16-split HMMA, output split bf16
    k_hmma2<<<dim3(2, BATCH / 128), 256, SM_TOT_US * 2>>>(
        x, nullptr, nullptr, w1h, w1l, b1, nullptr, h1h, h1l, 784, 800, 512);
    // L2: [B,512] -> [B,256], bf16 input, fp32 output
    k_hmma2<<<dim3(1, BATCH / 128), 256, SM_TOT_US * 2>>>(
        nullptr, h1h, h1l, w2h, w2l, b2, mid, nullptr, nullptr, 512, 512, 256);
    // router
    k_router<<<BATCH / 8, 256>>>(mid, Wr, br, pw);
    // fused grouped middle layer
    k_mid<<<dim3(2, BATCH / 128), 256>>>(mid, W3, b3, pw, mo);
    // fused L4/L5/L6
    k_tail<<<BATCH / 32, 256, TAIL_SMEM_FLOATS * 4>>>(mo, W4, b4, W5, b5, W6, b6, out);
}